// round 14
// baseline (speedup 1.0000x reference)
#include <cuda_runtime.h>

#define BB 16
#define NN 64
#define CC 32
#define NLVL 4
#define NB 60
#define NE 2048
#define NPAIR (BB*NN*NN)

typedef unsigned long long u64;

__device__ __forceinline__ u64 ffma2(u64 a, u64 b, u64 c) {
    u64 d; asm("fma.rn.f32x2 %0, %1, %2, %3;" : "=l"(d) : "l"(a), "l"(b), "l"(c)); return d;
}
__device__ __forceinline__ u64 addf2(u64 a, u64 b) {
    u64 d; asm("add.rn.f32x2 %0, %1, %2;" : "=l"(d) : "l"(a), "l"(b)); return d;
}
__device__ __forceinline__ u64 packf2(float lo, float hi) {
    u64 r; asm("mov.b64 %0, {%1, %2};" : "=l"(r) : "f"(lo), "f"(hi)); return r;
}
__device__ __forceinline__ u64 dupf2(float v) {
    u64 r; asm("mov.b64 %0, {%1, %1};" : "=l"(r) : "f"(v)); return r;
}
__device__ __forceinline__ float2 unpackf2(u64 v) {
    float2 r; asm("mov.b64 {%0, %1}, %2;" : "=f"(r.x), "=f"(r.y) : "l"(v)); return r;
}

// ---------------- device scratch (static; no allocs) ----------------
__device__ float g_a[2][BB*NN*CC];
__device__ float g_rep[4][BB*NN*7*CC];
__device__ float g_edge[4][NPAIR*CC];
__device__ float g_sph[NPAIR*16];
__device__ float2 g_fe[NPAIR];            // {frac, bitcast(e0)}
__device__ float g_part4[BB*NN*4];
__device__ float2 g_tab2[(NE+2)*512];     // {val[e], val[e+1]}, row NE+1 = zeros

// ---------------- rad*cut table, basis inline ----------------
__global__ void __launch_bounds__(256) k_table(const float* __restrict__ W_rad) {
    __shared__ float sW[NB*CC];
    __shared__ float sb[64*NB];
    int s   = blockIdx.y;
    int e0b = blockIdx.x * 64;
    int tid = threadIdx.x;
    const float* wr = W_rad + s*NB*CC;
    for (int idx = tid; idx < NB*CC; idx += 256) sW[idx] = wr[idx];
    for (int idx = tid; idx < 64*NB; idx += 256) {
        int row = idx / NB, k = idx - row*NB;
        float r = (float)(e0b + row) * (5.0f/NE);
        float d = r - (float)k * (5.0f/59.0f);
        sb[idx] = expf(-36.0f * d * d);
    }
    __syncthreads();
    int c = tid & 31, eg = tid >> 5;
    float acc[8];
    #pragma unroll
    for (int t = 0; t < 8; ++t) acc[t] = 0.0f;
    for (int k = 0; k < NB; ++k) {
        float wv = sW[k*CC + c];
        #pragma unroll
        for (int t = 0; t < 8; ++t)
            acc[t] = fmaf(sb[(eg*8 + t)*NB + k], wv, acc[t]);
    }
    #pragma unroll
    for (int t = 0; t < 8; ++t) {
        int e = e0b + eg*8 + t;
        if (e <= NE+1) {
            float r = (float)e * (5.0f/NE);
            float cut = 1.0f / (1.0f + __expf((r - 3.0f) * 2.0f));
            float v = (e <= NE) ? acc[t] * cut : 0.0f;   // row NE+1 = hard zero
            g_tab2[e*512 + s*32 + c].x = v;
            if (e > 0) g_tab2[(e-1)*512 + s*32 + c].y = v;
        }
    }
}

// ---------------- geometry + fused input featurization ----------------
__global__ void k_geom(const float* __restrict__ pos,
                       const float* __restrict__ oh, const int* __restrict__ charges,
                       const float* __restrict__ W_in, const float* __restrict__ b_in) {
    if (blockIdx.x >= 256) {   // fused a0 (BB*NN*CC = 32768 threads) + zero g_part4
        int t = (blockIdx.x - 256)*256 + threadIdx.x;   // 0..32767
        int c = t & 31, n = t >> 5;
        float ch = (float)charges[n] * (1.0f/9.0f);
        float p1 = ch, p2 = ch*ch;
        float acc = b_in[c];
        #pragma unroll
        for (int s = 0; s < 5; ++s) {
            float o = oh[n*5 + s];
            acc += o * (W_in[(s*3+0)*CC + c] + p1*W_in[(s*3+1)*CC + c] + p2*W_in[(s*3+2)*CC + c]);
        }
        g_a[0][t] = acc;
        g_rep[0][(n*7 + 0)*CC + c] = acc;
        if (t < BB*NN*4) g_part4[t] = 0.0f;
        return;
    }
    int t = blockIdx.x*256 + threadIdx.x;
    int b = t >> 12, i = (t >> 6) & 63, j = t & 63;
    const float* pi = pos + (b*NN+i)*3;
    const float* pj = pos + (b*NN+j)*3;
    float dx = pi[0]-pj[0], dy = pi[1]-pj[1], dz = pi[2]-pj[2];
    float r = sqrtf(dx*dx + dy*dy + dz*dz + 1e-12f);
    float inv = 1.0f / r;
    float x = dx*inv, y = dy*inv, z = dz*inv;

    bool masked = (i == j) || (r <= 1e-4f) || (r >= 5.0f);
    float fidx = r * ((float)NE / 5.0f);
    int e0 = (int)fidx;
    if (e0 > NE-1) e0 = NE-1;
    float fr = fidx - (float)e0;
    if (fr > 1.0f) fr = 1.0f;
    if (masked) { e0 = NE+1; fr = 0.0f; }
    g_fe[t] = make_float2(fr, __int_as_float(e0));

    float xx = x*x, yy = y*y, zz = z*z;
    float4 s0 = make_float4(1.0f, x, y, z);
    float4 s1 = make_float4(x*y, y*z, 3.0f*zz - 1.0f, x*z);
    float4 s2 = make_float4(xx - yy, y*(3.0f*xx - yy), x*y*z, y*(5.0f*zz - 1.0f));
    float4 s3 = make_float4(z*(5.0f*zz - 3.0f), x*(5.0f*zz - 1.0f),
                            z*(xx - yy), x*(xx - 3.0f*yy));
    float4* o = (float4*)(g_sph + t*16);
    o[0] = s0; o[1] = s1; o[2] = s2; o[3] = s3;
}

// ---------------- per-warp (atom, l) work: f32x2 inner loop (R8 exact), smem-weight epilogue
template<int L, bool HP, bool ST>
__device__ __forceinline__ void atom_warp(
    const float* sa, const float* sWE, const float2* fe,
    float* sphw,                 // warp-private 512-float slice (sph + scratch)
    const float* sWA, const float* sWS, const float* sWT,
    float* ge, const float2* tabbase, int i_local, int atom, int lane, int lvl, int s,
    float* anext)
{
    const int M = 2*L + 1;

    u64 vreg2[16];
    #pragma unroll
    for (int dp = 0; dp < 16; ++dp)
        vreg2[dp] = packf2(sa[i_local*CC + 2*dp]     * sWE[(2*dp)*CC + lane],
                           sa[i_local*CC + 2*dp + 1] * sWE[(2*dp+1)*CC + lane]);

    u64  accP[4] = {0ull, 0ull, 0ull, 0ull};
    float acc0 = 0.0f;

    // depth-2 rolling prefetch on table + previous-edge loads
    float2 fe0 = fe[0], fe1 = fe[1];
    float2 tv0 = tabbase[__float_as_int(fe0.y)*512];
    float2 tv1 = tabbase[__float_as_int(fe1.y)*512];
    float gp0 = HP ? ge[lane]      : 0.0f;
    float gp1 = HP ? ge[CC + lane] : 0.0f;

    #pragma unroll 4
    for (int jt = 0; jt < 64; ++jt) {
        float2 fen = make_float2(0.0f, 0.0f);
        float2 tvn = make_float2(0.0f, 0.0f);
        float  gpn = 0.0f;
        if (jt < 62) {
            fen = fe[jt + 2];
            tvn = tabbase[__float_as_int(fen.y)*512];
            if (HP) gpn = ge[(jt+2)*CC + lane];
        }
        const ulonglong2* aj = (const ulonglong2*)(sa + jt*CC);
        u64 aA = 0, aB = 0, aC = 0, aD = 0;
        aA = ffma2(aj[0].x, vreg2[0],  aA);  aB = ffma2(aj[0].y, vreg2[1],  aB);
        aC = ffma2(aj[1].x, vreg2[2],  aC);  aD = ffma2(aj[1].y, vreg2[3],  aD);
        aA = ffma2(aj[2].x, vreg2[4],  aA);  aB = ffma2(aj[2].y, vreg2[5],  aB);
        aC = ffma2(aj[3].x, vreg2[6],  aC);  aD = ffma2(aj[3].y, vreg2[7],  aD);
        aA = ffma2(aj[4].x, vreg2[8],  aA);  aB = ffma2(aj[4].y, vreg2[9],  aB);
        aC = ffma2(aj[5].x, vreg2[10], aC);  aD = ffma2(aj[5].y, vreg2[11], aD);
        aA = ffma2(aj[6].x, vreg2[12], aA);  aB = ffma2(aj[6].y, vreg2[13], aB);
        aC = ffma2(aj[7].x, vreg2[14], aC);  aD = ffma2(aj[7].y, vreg2[15], aD);
        u64 sT = addf2(addf2(aA, aB), addf2(aC, aD));
        float2 fsum = unpackf2(sT);
        float eacc = (fsum.x + fsum.y) + gp0;
        float rad  = fmaf(fe0.x, tv0.y - tv0.x, tv0.x);
        float edge = rad * eacc;
        if (ST) ge[jt*CC + lane] = edge;

        if (L == 0) {
            acc0 += edge;
        } else {
            u64 e2 = dupf2(edge);
            const ulonglong2* sp2 = (const ulonglong2*)(sphw + jt*8);
            accP[0] = ffma2(e2, sp2[0].x, accP[0]);
            accP[1] = ffma2(e2, sp2[0].y, accP[1]);
            if (M > 4) {
                accP[2] = ffma2(e2, sp2[1].x, accP[2]);
                if (M > 6) accP[3] = ffma2(e2, sp2[1].y, accP[3]);
            }
        }
        fe0 = fe1; fe1 = fen;
        tv0 = tv1; tv1 = tvn;
        gp0 = gp1; gp1 = gpn;
    }

    float accm[7];
    if (L == 0) {
        accm[0] = acc0;
    } else {
        float2 u0 = unpackf2(accP[0]), u1 = unpackf2(accP[1]);
        accm[0] = u0.x; accm[1] = u0.y; accm[2] = u1.x;
        if (M > 3) accm[3] = u1.y;
        if (M > 4) {
            float2 u2 = unpackf2(accP[2]);
            accm[4] = u2.x;
            if (M > 5) accm[5] = u2.y;
            if (M > 6) { float2 u3 = unpackf2(accP[3]); accm[6] = u3.x; }
        }
    }

    // ---- per-warp epilogue: weights from SMEM (staged once per block) ----
    __syncwarp();
    float* wmsg = sphw;
    float* sold = sphw + 256;
    bool has_self = (lvl > 0) || (L == 0);
    #pragma unroll
    for (int m = 0; m < M; ++m) {
        wmsg[m*32 + lane] = accm[m];
        sold[m*32 + lane] = has_self ? g_rep[L][(atom*7 + m)*CC + lane] : 0.0f;
    }
    __syncwarp();

    float f, s2 = 0.0f, rep0 = 0.0f;
    #pragma unroll
    for (int m = 0; m < M; ++m) {
        float r = 0.0f, r2 = 0.0f;
        #pragma unroll
        for (int c = 0; c < CC; ++c) {
            r  = fmaf(wmsg[m*32 + c], sWA[c*CC + lane], r);
            r2 = fmaf(sold[m*32 + c], sWS[c*CC + lane], r2);
        }
        r += r2;
        g_rep[L][(atom*7 + m)*CC + lane] = r;
        if (m == 0) rep0 = r;
        s2 = fmaf(r, r, s2);
    }
    if (L == 0) {
        anext[atom*CC + lane] = rep0;
        f = rep0;
    } else {
        f = sqrtf(s2 + 1e-12f);
    }
    float part = f * sWT[lane];
    #pragma unroll
    for (int off = 16; off; off >>= 1)
        part += __shfl_down_sync(0xffffffffu, part, off);
    if (lane == 0) g_part4[atom*4 + L] += part;
}

// ---------------- one (4-atom group, l) block; warp = one atom ----------------
__global__ void __launch_bounds__(128, 7) k_level(int lvl,
    const float* __restrict__ W_edge, const float* __restrict__ W_agg,
    const float* __restrict__ W_self, const float* __restrict__ W_top)
{
    __shared__ float  sa[NN*CC];        // 8 KB
    __shared__ float  sWE[CC*CC];       // 4 KB
    __shared__ float  sWA[CC*CC];       // 4 KB (W_agg staged)
    __shared__ float  sWS[CC*CC];       // 4 KB (W_self staged)
    __shared__ float  sWT[CC];          // 128 B (W_top staged)
    __shared__ float2 sfe[4*NN];        // 2 KB
    __shared__ float  ssph[4*NN*8];     // 8 KB; warp slices, reused in epilogue

    const float* acur  = g_a[lvl & 1];
    float*       anext = g_a[(lvl + 1) & 1];

    int blk = blockIdx.x;
    int l  = blk & 3;
    int g4 = blk >> 2;
    int b  = g4 >> 4;
    const int M = 2*l + 1;
    int tid = threadIdx.x, w = tid >> 5, lane = tid & 31;
    int atom0 = g4*4;
    int s = lvl*4 + l;

    for (int idx = tid; idx < NN*CC/4; idx += 128)
        ((float4*)sa)[idx] = ((const float4*)(acur + b*NN*CC))[idx];
    {
        const float4* we = (const float4*)(W_edge + s*CC*CC);
        const float4* wa = (const float4*)(W_agg  + s*CC*CC);
        const float4* ws = (const float4*)(W_self + s*CC*CC);
        for (int idx = tid; idx < CC*CC/4; idx += 128) {
            ((float4*)sWE)[idx] = we[idx];
            ((float4*)sWA)[idx] = wa[idx];
            ((float4*)sWS)[idx] = ws[idx];
        }
    }
    if (tid < CC) sWT[tid] = W_top[s*CC + tid];
    for (int t = tid; t < 4*NN; t += 128)
        sfe[t] = g_fe[atom0*NN + t];
    if (l > 0) {
        for (int t = tid; t < 4*NN*8; t += 128) {
            int wi = t >> 9, rem = t & 511, j = rem >> 3, m = rem & 7;
            ssph[t] = (m < M) ? g_sph[((atom0 + wi)*NN + j)*16 + l*l + m] : 0.0f;
        }
    }
    __syncthreads();

    int atom = atom0 + w;
    int i_local = atom & 63;
    float* ge = g_edge[l] + atom*NN*CC;
    const float2* tabbase = g_tab2 + s*32 + lane;
    const float2* fe = sfe + w*NN;
    float* sphw = ssph + w*512;

    if (lvl == 0) {
        switch (l) {
            case 0: atom_warp<0,false,true>(sa,sWE,fe,sphw,sWA,sWS,sWT,ge,tabbase,i_local,atom,lane,lvl,s,anext); break;
            case 1: atom_warp<1,false,true>(sa,sWE,fe,sphw,sWA,sWS,sWT,ge,tabbase,i_local,atom,lane,lvl,s,anext); break;
            case 2: atom_warp<2,false,true>(sa,sWE,fe,sphw,sWA,sWS,sWT,ge,tabbase,i_local,atom,lane,lvl,s,anext); break;
            default:atom_warp<3,false,true>(sa,sWE,fe,sphw,sWA,sWS,sWT,ge,tabbase,i_local,atom,lane,lvl,s,anext); break;
        }
    } else if (lvl < 3) {
        switch (l) {
            case 0: atom_warp<0,true,true >(sa,sWE,fe,sphw,sWA,sWS,sWT,ge,tabbase,i_local,atom,lane,lvl,s,anext); break;
            case 1: atom_warp<1,true,true >(sa,sWE,fe,sphw,sWA,sWS,sWT,ge,tabbase,i_local,atom,lane,lvl,s,anext); break;
            case 2: atom_warp<2,true,true >(sa,sWE,fe,sphw,sWA,sWS,sWT,ge,tabbase,i_local,atom,lane,lvl,s,anext); break;
            default:atom_warp<3,true,true >(sa,sWE,fe,sphw,sWA,sWS,sWT,ge,tabbase,i_local,atom,lane,lvl,s,anext); break;
        }
    } else {
        switch (l) {
            case 0: atom_warp<0,true,false>(sa,sWE,fe,sphw,sWA,sWS,sWT,ge,tabbase,i_local,atom,lane,lvl,s,anext); break;
            case 1: atom_warp<1,true,false>(sa,sWE,fe,sphw,sWA,sWS,sWT,ge,tabbase,i_local,atom,lane,lvl,s,anext); break;
            case 2: atom_warp<2,true,false>(sa,sWE,fe,sphw,sWA,sWS,sWT,ge,tabbase,i_local,atom,lane,lvl,s,anext); break;
            default:atom_warp<3,true,false>(sa,sWE,fe,sphw,sWA,sWS,sWT,ge,tabbase,i_local,atom,lane,lvl,s,anext); break;
        }
    }
}

// ---------------- output ----------------
__global__ void k_out(float* __restrict__ out, const float* __restrict__ b_top) {
    __shared__ float sh[256];
    int b = blockIdx.x, t = threadIdx.x;
    sh[t] = g_part4[b*256 + t];
    __syncthreads();
    #pragma unroll
    for (int off = 128; off; off >>= 1) {
        if (t < off) sh[t] += sh[t + off];
        __syncthreads();
    }
    if (t == 0) out[b] = sh[0] + b_top[0];
}

// ---------------- launch ----------------
extern "C" void kernel_launch(void* const* d_in, const int* in_sizes, int n_in,
                              void* d_out, int out_size) {
    const float* pos     = (const float*)d_in[0];
    const float* oh      = (const float*)d_in[1];
    const int*   charges = (const int*)  d_in[2];
    const float* W_in    = (const float*)d_in[5];
    const float* b_in    = (const float*)d_in[6];
    const float* W_rad   = (const float*)d_in[7];
    const float* W_edge  = (const float*)d_in[8];
    const float* W_agg   = (const float*)d_in[9];
    const float* W_self  = (const float*)d_in[10];
    const float* W_top   = (const float*)d_in[11];
    const float* b_top   = (const float*)d_in[12];

    k_table<<<dim3(33, 16), 256>>>(W_rad);
    k_geom<<<256 + 128, 256>>>(pos, oh, charges, W_in, b_in);
    for (int lvl = 0; lvl < NLVL; ++lvl)
        k_level<<<BB*NN, 128>>>(lvl, W_edge, W_agg, W_self, W_top);
    k_out<<<BB, 256>>>((float*)d_out, b_top);
}

// round 15
// speedup vs baseline: 1.0239x; 1.0239x over previous
#include <cuda_runtime.h>

#define BB 16
#define NN 64
#define CC 32
#define NLVL 4
#define NB 60
#define NE 2048
#define NPAIR (BB*NN*NN)

typedef unsigned long long u64;

__device__ __forceinline__ u64 ffma2(u64 a, u64 b, u64 c) {
    u64 d; asm("fma.rn.f32x2 %0, %1, %2, %3;" : "=l"(d) : "l"(a), "l"(b), "l"(c)); return d;
}
__device__ __forceinline__ u64 addf2(u64 a, u64 b) {
    u64 d; asm("add.rn.f32x2 %0, %1, %2;" : "=l"(d) : "l"(a), "l"(b)); return d;
}
__device__ __forceinline__ u64 packf2(float lo, float hi) {
    u64 r; asm("mov.b64 %0, {%1, %2};" : "=l"(r) : "f"(lo), "f"(hi)); return r;
}
__device__ __forceinline__ u64 dupf2(float v) {
    u64 r; asm("mov.b64 %0, {%1, %1};" : "=l"(r) : "f"(v)); return r;
}
__device__ __forceinline__ float2 unpackf2(u64 v) {
    float2 r; asm("mov.b64 {%0, %1}, %2;" : "=f"(r.x), "=f"(r.y) : "l"(v)); return r;
}

// ---------------- device scratch (static; no allocs) ----------------
__device__ float g_a[2][BB*NN*CC];
__device__ float g_rep[4][BB*NN*7*CC];
__device__ float g_edge[4][NPAIR*CC];
__device__ float g_sph[NPAIR*16];
__device__ float2 g_fe[NPAIR];            // {frac, bitcast(e0*4096 byte offset)}
__device__ float g_part4[BB*NN*4];
__device__ float2 g_tab2[(NE+2)*512];     // {val[e], val[e+1]}, row NE+1 = zeros

// ---------------- rad*cut table, basis inline ----------------
__global__ void __launch_bounds__(256) k_table(const float* __restrict__ W_rad) {
    __shared__ float sW[NB*CC];
    __shared__ float sb[64*NB];
    int s   = blockIdx.y;
    int e0b = blockIdx.x * 64;
    int tid = threadIdx.x;
    const float* wr = W_rad + s*NB*CC;
    for (int idx = tid; idx < NB*CC; idx += 256) sW[idx] = wr[idx];
    for (int idx = tid; idx < 64*NB; idx += 256) {
        int row = idx / NB, k = idx - row*NB;
        float r = (float)(e0b + row) * (5.0f/NE);
        float d = r - (float)k * (5.0f/59.0f);
        sb[idx] = expf(-36.0f * d * d);
    }
    __syncthreads();
    int c = tid & 31, eg = tid >> 5;
    float acc[8];
    #pragma unroll
    for (int t = 0; t < 8; ++t) acc[t] = 0.0f;
    for (int k = 0; k < NB; ++k) {
        float wv = sW[k*CC + c];
        #pragma unroll
        for (int t = 0; t < 8; ++t)
            acc[t] = fmaf(sb[(eg*8 + t)*NB + k], wv, acc[t]);
    }
    #pragma unroll
    for (int t = 0; t < 8; ++t) {
        int e = e0b + eg*8 + t;
        if (e <= NE+1) {
            float r = (float)e * (5.0f/NE);
            float cut = 1.0f / (1.0f + __expf((r - 3.0f) * 2.0f));
            float v = (e <= NE) ? acc[t] * cut : 0.0f;   // row NE+1 = hard zero
            g_tab2[e*512 + s*32 + c].x = v;
            if (e > 0) g_tab2[(e-1)*512 + s*32 + c].y = v;
        }
    }
}

// ---------------- geometry + fused input featurization ----------------
__global__ void k_geom(const float* __restrict__ pos,
                       const float* __restrict__ oh, const int* __restrict__ charges,
                       const float* __restrict__ W_in, const float* __restrict__ b_in) {
    if (blockIdx.x >= 256) {   // fused a0 (BB*NN*CC = 32768 threads) + zero g_part4
        int t = (blockIdx.x - 256)*256 + threadIdx.x;   // 0..32767
        int c = t & 31, n = t >> 5;
        float ch = (float)charges[n] * (1.0f/9.0f);
        float p1 = ch, p2 = ch*ch;
        float acc = b_in[c];
        #pragma unroll
        for (int s = 0; s < 5; ++s) {
            float o = oh[n*5 + s];
            acc += o * (W_in[(s*3+0)*CC + c] + p1*W_in[(s*3+1)*CC + c] + p2*W_in[(s*3+2)*CC + c]);
        }
        g_a[0][t] = acc;
        g_rep[0][(n*7 + 0)*CC + c] = acc;
        if (t < BB*NN*4) g_part4[t] = 0.0f;
        return;
    }
    int t = blockIdx.x*256 + threadIdx.x;
    int b = t >> 12, i = (t >> 6) & 63, j = t & 63;
    const float* pi = pos + (b*NN+i)*3;
    const float* pj = pos + (b*NN+j)*3;
    float dx = pi[0]-pj[0], dy = pi[1]-pj[1], dz = pi[2]-pj[2];
    float r = sqrtf(dx*dx + dy*dy + dz*dz + 1e-12f);
    float inv = 1.0f / r;
    float x = dx*inv, y = dy*inv, z = dz*inv;

    bool masked = (i == j) || (r <= 1e-4f) || (r >= 5.0f);
    float fidx = r * ((float)NE / 5.0f);
    int e0 = (int)fidx;
    if (e0 > NE-1) e0 = NE-1;
    float fr = fidx - (float)e0;
    if (fr > 1.0f) fr = 1.0f;
    if (masked) { e0 = NE+1; fr = 0.0f; }
    g_fe[t] = make_float2(fr, __int_as_float(e0 * 4096));   // pre-scaled byte offset (512 float2 = 4096 B/row)

    float xx = x*x, yy = y*y, zz = z*z;
    float4 s0 = make_float4(1.0f, x, y, z);
    float4 s1 = make_float4(x*y, y*z, 3.0f*zz - 1.0f, x*z);
    float4 s2 = make_float4(xx - yy, y*(3.0f*xx - yy), x*y*z, y*(5.0f*zz - 1.0f));
    float4 s3 = make_float4(z*(5.0f*zz - 3.0f), x*(5.0f*zz - 1.0f),
                            z*(xx - yy), x*(xx - 3.0f*yy));
    float4* o = (float4*)(g_sph + t*16);
    o[0] = s0; o[1] = s1; o[2] = s2; o[3] = s3;
}

__device__ __forceinline__ float2 tab_at(const char* tabbase, int byteoff) {
    return *(const float2*)(tabbase + byteoff);
}

// ---------------- per-warp (atom, l) work: f32x2 inner loop (R8 + addr trims) ---------
template<int L, bool HP, bool ST>
__device__ __forceinline__ void atom_warp(
    const float* sa, const float* sWE, const float2* fe,
    float* sphw,                 // warp-private 512-float slice (sph + scratch)
    float* ge, const char* tabbase, int i_local, int atom, int lane, int lvl, int s,
    const float* __restrict__ W_agg, const float* __restrict__ W_self,
    const float* __restrict__ W_top, float* anext)
{
    const int M = 2*L + 1;

    u64 vreg2[16];
    #pragma unroll
    for (int dp = 0; dp < 16; ++dp)
        vreg2[dp] = packf2(sa[i_local*CC + 2*dp]     * sWE[(2*dp)*CC + lane],
                           sa[i_local*CC + 2*dp + 1] * sWE[(2*dp+1)*CC + lane]);

    u64  accP[4] = {0ull, 0ull, 0ull, 0ull};
    float acc0 = 0.0f;

    // depth-2 rolling prefetch; incremental pointers for ge (store + prefetch)
    float2 fe0 = fe[0], fe1 = fe[1];
    float2 tv0 = tab_at(tabbase, __float_as_int(fe0.y));
    float2 tv1 = tab_at(tabbase, __float_as_int(fe1.y));
    float* gw = ge + lane;                 // write ptr (jt)
    const float* gr = ge + 2*CC + lane;    // prefetch ptr (jt+2)
    float gp0 = HP ? gw[0]  : 0.0f;
    float gp1 = HP ? gw[CC] : 0.0f;

    #pragma unroll 4
    for (int jt = 0; jt < 64; ++jt) {
        float2 fen = make_float2(0.0f, 0.0f);
        float2 tvn = make_float2(0.0f, 0.0f);
        float  gpn = 0.0f;
        if (jt < 62) {
            fen = fe[jt + 2];
            tvn = tab_at(tabbase, __float_as_int(fen.y));
            if (HP) gpn = *gr;
        }
        const ulonglong2* aj = (const ulonglong2*)(sa + jt*CC);
        u64 aA = 0, aB = 0, aC = 0, aD = 0;
        aA = ffma2(aj[0].x, vreg2[0],  aA);  aB = ffma2(aj[0].y, vreg2[1],  aB);
        aC = ffma2(aj[1].x, vreg2[2],  aC);  aD = ffma2(aj[1].y, vreg2[3],  aD);
        aA = ffma2(aj[2].x, vreg2[4],  aA);  aB = ffma2(aj[2].y, vreg2[5],  aB);
        aC = ffma2(aj[3].x, vreg2[6],  aC);  aD = ffma2(aj[3].y, vreg2[7],  aD);
        aA = ffma2(aj[4].x, vreg2[8],  aA);  aB = ffma2(aj[4].y, vreg2[9],  aB);
        aC = ffma2(aj[5].x, vreg2[10], aC);  aD = ffma2(aj[5].y, vreg2[11], aD);
        aA = ffma2(aj[6].x, vreg2[12], aA);  aB = ffma2(aj[6].y, vreg2[13], aB);
        aC = ffma2(aj[7].x, vreg2[14], aC);  aD = ffma2(aj[7].y, vreg2[15], aD);
        u64 sT = addf2(addf2(aA, aB), addf2(aC, aD));
        float2 fsum = unpackf2(sT);
        float eacc = (fsum.x + fsum.y) + gp0;
        float rad  = fmaf(fe0.x, tv0.y - tv0.x, tv0.x);
        float edge = rad * eacc;
        if (ST) *gw = edge;
        gw += CC; gr += CC;

        if (L == 0) {
            acc0 += edge;
        } else {
            u64 e2 = dupf2(edge);
            const ulonglong2* sp2 = (const ulonglong2*)(sphw + jt*8);
            accP[0] = ffma2(e2, sp2[0].x, accP[0]);
            accP[1] = ffma2(e2, sp2[0].y, accP[1]);
            if (M > 4) {
                accP[2] = ffma2(e2, sp2[1].x, accP[2]);
                if (M > 6) accP[3] = ffma2(e2, sp2[1].y, accP[3]);
            }
        }
        fe0 = fe1; fe1 = fen;
        tv0 = tv1; tv1 = tvn;
        gp0 = gp1; gp1 = gpn;
    }

    float accm[7];
    if (L == 0) {
        accm[0] = acc0;
    } else {
        float2 u0 = unpackf2(accP[0]), u1 = unpackf2(accP[1]);
        accm[0] = u0.x; accm[1] = u0.y; accm[2] = u1.x;
        if (M > 3) accm[3] = u1.y;
        if (M > 4) {
            float2 u2 = unpackf2(accP[2]);
            accm[4] = u2.x;
            if (M > 5) accm[5] = u2.y;
            if (M > 6) { float2 u3 = unpackf2(accP[3]); accm[6] = u3.x; }
        }
    }

    // ---- per-warp epilogue (R8 exact: weights via LDG, L1-resident) ----
    __syncwarp();
    float* wmsg = sphw;
    float* sold = sphw + 256;
    bool has_self = (lvl > 0) || (L == 0);
    #pragma unroll
    for (int m = 0; m < M; ++m) {
        wmsg[m*32 + lane] = accm[m];
        sold[m*32 + lane] = has_self ? g_rep[L][(atom*7 + m)*CC + lane] : 0.0f;
    }
    __syncwarp();

    const float* wa  = W_agg  + s*CC*CC;
    const float* wsf = W_self + s*CC*CC;
    float f, s2 = 0.0f, rep0 = 0.0f;
    #pragma unroll
    for (int m = 0; m < M; ++m) {
        float r = 0.0f, r2 = 0.0f;
        #pragma unroll
        for (int c = 0; c < CC; ++c) {
            r  = fmaf(wmsg[m*32 + c], wa [c*CC + lane], r);
            r2 = fmaf(sold[m*32 + c], wsf[c*CC + lane], r2);
        }
        r += r2;
        g_rep[L][(atom*7 + m)*CC + lane] = r;
        if (m == 0) rep0 = r;
        s2 = fmaf(r, r, s2);
    }
    if (L == 0) {
        anext[atom*CC + lane] = rep0;
        f = rep0;
    } else {
        f = sqrtf(s2 + 1e-12f);
    }
    float part = f * W_top[s*CC + lane];
    #pragma unroll
    for (int off = 16; off; off >>= 1)
        part += __shfl_down_sync(0xffffffffu, part, off);
    if (lane == 0) g_part4[atom*4 + L] += part;
}

// ---------------- one (4-atom group, l) block; warp = one atom ----------------
__global__ void __launch_bounds__(128, 7) k_level(int lvl,
    const float* __restrict__ W_edge, const float* __restrict__ W_agg,
    const float* __restrict__ W_self, const float* __restrict__ W_top)
{
    __shared__ float  sa[NN*CC];        // 8 KB
    __shared__ float  sWE[CC*CC];       // 4 KB
    __shared__ float2 sfe[4*NN];        // 2 KB
    __shared__ float  ssph[4*NN*8];     // 8 KB; warp slices, reused in epilogue

    const float* acur  = g_a[lvl & 1];
    float*       anext = g_a[(lvl + 1) & 1];

    int blk = blockIdx.x;
    int l  = blk & 3;
    int g4 = blk >> 2;
    int b  = g4 >> 4;
    const int M = 2*l + 1;
    int tid = threadIdx.x, w = tid >> 5, lane = tid & 31;
    int atom0 = g4*4;
    int s = lvl*4 + l;

    for (int idx = tid; idx < NN*CC/4; idx += 128)
        ((float4*)sa)[idx] = ((const float4*)(acur + b*NN*CC))[idx];
    {
        const float4* wsrc = (const float4*)(W_edge + s*CC*CC);
        for (int idx = tid; idx < CC*CC/4; idx += 128)
            ((float4*)sWE)[idx] = wsrc[idx];
    }
    for (int t = tid; t < 4*NN; t += 128)
        sfe[t] = g_fe[atom0*NN + t];
    if (l > 0) {
        for (int t = tid; t < 4*NN*8; t += 128) {
            int wi = t >> 9, rem = t & 511, j = rem >> 3, m = rem & 7;
            ssph[t] = (m < M) ? g_sph[((atom0 + wi)*NN + j)*16 + l*l + m] : 0.0f;
        }
    }
    __syncthreads();

    int atom = atom0 + w;
    int i_local = atom & 63;
    float* ge = g_edge[l] + atom*NN*CC;
    const char* tabbase = (const char*)(g_tab2 + s*32 + lane);
    const float2* fe = sfe + w*NN;
    float* sphw = ssph + w*512;

    if (lvl == 0) {
        switch (l) {
            case 0: atom_warp<0,false,true>(sa,sWE,fe,sphw,ge,tabbase,i_local,atom,lane,lvl,s,W_agg,W_self,W_top,anext); break;
            case 1: atom_warp<1,false,true>(sa,sWE,fe,sphw,ge,tabbase,i_local,atom,lane,lvl,s,W_agg,W_self,W_top,anext); break;
            case 2: atom_warp<2,false,true>(sa,sWE,fe,sphw,ge,tabbase,i_local,atom,lane,lvl,s,W_agg,W_self,W_top,anext); break;
            default:atom_warp<3,false,true>(sa,sWE,fe,sphw,ge,tabbase,i_local,atom,lane,lvl,s,W_agg,W_self,W_top,anext); break;
        }
    } else if (lvl < 3) {
        switch (l) {
            case 0: atom_warp<0,true,true >(sa,sWE,fe,sphw,ge,tabbase,i_local,atom,lane,lvl,s,W_agg,W_self,W_top,anext); break;
            case 1: atom_warp<1,true,true >(sa,sWE,fe,sphw,ge,tabbase,i_local,atom,lane,lvl,s,W_agg,W_self,W_top,anext); break;
            case 2: atom_warp<2,true,true >(sa,sWE,fe,sphw,ge,tabbase,i_local,atom,lane,lvl,s,W_agg,W_self,W_top,anext); break;
            default:atom_warp<3,true,true >(sa,sWE,fe,sphw,ge,tabbase,i_local,atom,lane,lvl,s,W_agg,W_self,W_top,anext); break;
        }
    } else {
        switch (l) {
            case 0: atom_warp<0,true,false>(sa,sWE,fe,sphw,ge,tabbase,i_local,atom,lane,lvl,s,W_agg,W_self,W_top,anext); break;
            case 1: atom_warp<1,true,false>(sa,sWE,fe,sphw,ge,tabbase,i_local,atom,lane,lvl,s,W_agg,W_self,W_top,anext); break;
            case 2: atom_warp<2,true,false>(sa,sWE,fe,sphw,ge,tabbase,i_local,atom,lane,lvl,s,W_agg,W_self,W_top,anext); break;
            default:atom_warp<3,true,false>(sa,sWE,fe,sphw,ge,tabbase,i_local,atom,lane,lvl,s,W_agg,W_self,W_top,anext); break;
        }
    }
}

// ---------------- output ----------------
__global__ void k_out(float* __restrict__ out, const float* __restrict__ b_top) {
    __shared__ float sh[256];
    int b = blockIdx.x, t = threadIdx.x;
    sh[t] = g_part4[b*256 + t];
    __syncthreads();
    #pragma unroll
    for (int off = 128; off; off >>= 1) {
        if (t < off) sh[t] += sh[t + off];
        __syncthreads();
    }
    if (t == 0) out[b] = sh[0] + b_top[0];
}

// ---------------- launch ----------------
extern "C" void kernel_launch(void* const* d_in, const int* in_sizes, int n_in,
                              void* d_out, int out_size) {
    const float* pos     = (const float*)d_in[0];
    const float* oh      = (const float*)d_in[1];
    const int*   charges = (const int*)  d_in[2];
    const float* W_in    = (const float*)d_in[5];
    const float* b_in    = (const float*)d_in[6];
    const float* W_rad   = (const float*)d_in[7];
    const float* W_edge  = (const float*)d_in[8];
    const float* W_agg   = (const float*)d_in[9];
    const float* W_self  = (const float*)d_in[10];
    const float* W_top   = (const float*)d_in[11];
    const float* b_top   = (const float*)d_in[12];

    k_table<<<dim3(33, 16), 256>>>(W_rad);
    k_geom<<<256 + 128, 256>>>(pos, oh, charges, W_in, b_in);
    for (int lvl = 0; lvl < NLVL; ++lvl)
        k_level<<<BB*NN, 128>>>(lvl, W_edge, W_agg, W_self, W_top);
    k_out<<<BB, 256>>>((float*)d_out, b_top);
}

// round 16
// speedup vs baseline: 1.1021x; 1.0764x over previous
#include <cuda_runtime.h>

#define BB 16
#define NN 64
#define CC 32
#define NLVL 4
#define NB 60
#define NE 2048
#define NPAIR (BB*NN*NN)

// ---------------- device scratch (static; no allocs) ----------------
__device__ float g_a[2][BB*NN*CC];
__device__ float g_rep[4][BB*NN*7*CC];
__device__ float g_edge[4][NPAIR*CC];
__device__ float g_sph[NPAIR*16];
__device__ float2 g_fe[NPAIR];            // {frac, bitcast(e0)}
__device__ float g_part4[BB*NN*4];
__device__ float2 g_tab2[(NE+2)*512];     // {val[e], val[e+1]}, row NE+1 = zeros

// ---------------- rad*cut table, basis inline ----------------
__global__ void __launch_bounds__(256) k_table(const float* __restrict__ W_rad) {
    __shared__ float sW[NB*CC];
    __shared__ float sb[64*NB];
    int s   = blockIdx.y;
    int e0b = blockIdx.x * 64;
    int tid = threadIdx.x;
    const float* wr = W_rad + s*NB*CC;
    for (int idx = tid; idx < NB*CC; idx += 256) sW[idx] = wr[idx];
    for (int idx = tid; idx < 64*NB; idx += 256) {
        int row = idx / NB, k = idx - row*NB;
        float r = (float)(e0b + row) * (5.0f/NE);
        float d = r - (float)k * (5.0f/59.0f);
        sb[idx] = expf(-36.0f * d * d);
    }
    __syncthreads();
    int c = tid & 31, eg = tid >> 5;
    float acc[8];
    #pragma unroll
    for (int t = 0; t < 8; ++t) acc[t] = 0.0f;
    for (int k = 0; k < NB; ++k) {
        float wv = sW[k*CC + c];
        #pragma unroll
        for (int t = 0; t < 8; ++t)
            acc[t] = fmaf(sb[(eg*8 + t)*NB + k], wv, acc[t]);
    }
    #pragma unroll
    for (int t = 0; t < 8; ++t) {
        int e = e0b + eg*8 + t;
        if (e <= NE+1) {
            float r = (float)e * (5.0f/NE);
            float cut = 1.0f / (1.0f + __expf((r - 3.0f) * 2.0f));
            float v = (e <= NE) ? acc[t] * cut : 0.0f;   // row NE+1 = hard zero
            g_tab2[e*512 + s*32 + c].x = v;
            if (e > 0) g_tab2[(e-1)*512 + s*32 + c].y = v;
        }
    }
}

// ---------------- geometry + fused input featurization ----------------
__global__ void k_geom(const float* __restrict__ pos,
                       const float* __restrict__ oh, const int* __restrict__ charges,
                       const float* __restrict__ W_in, const float* __restrict__ b_in) {
    if (blockIdx.x >= 256) {   // fused a0 (BB*NN*CC = 32768 threads) + zero g_part4
        int t = (blockIdx.x - 256)*256 + threadIdx.x;   // 0..32767
        int c = t & 31, n = t >> 5;
        float ch = (float)charges[n] * (1.0f/9.0f);
        float p1 = ch, p2 = ch*ch;
        float acc = b_in[c];
        #pragma unroll
        for (int s = 0; s < 5; ++s) {
            float o = oh[n*5 + s];
            acc += o * (W_in[(s*3+0)*CC + c] + p1*W_in[(s*3+1)*CC + c] + p2*W_in[(s*3+2)*CC + c]);
        }
        g_a[0][t] = acc;
        g_rep[0][(n*7 + 0)*CC + c] = acc;
        if (t < BB*NN*4) g_part4[t] = 0.0f;
        return;
    }
    int t = blockIdx.x*256 + threadIdx.x;
    int b = t >> 12, i = (t >> 6) & 63, j = t & 63;
    const float* pi = pos + (b*NN+i)*3;
    const float* pj = pos + (b*NN+j)*3;
    float dx = pi[0]-pj[0], dy = pi[1]-pj[1], dz = pi[2]-pj[2];
    float r = sqrtf(dx*dx + dy*dy + dz*dz + 1e-12f);
    float inv = 1.0f / r;
    float x = dx*inv, y = dy*inv, z = dz*inv;

    bool masked = (i == j) || (r <= 1e-4f) || (r >= 5.0f);
    float fidx = r * ((float)NE / 5.0f);
    int e0 = (int)fidx;
    if (e0 > NE-1) e0 = NE-1;
    float fr = fidx - (float)e0;
    if (fr > 1.0f) fr = 1.0f;
    if (masked) { e0 = NE+1; fr = 0.0f; }
    g_fe[t] = make_float2(fr, __int_as_float(e0));

    float xx = x*x, yy = y*y, zz = z*z;
    float4 s0 = make_float4(1.0f, x, y, z);
    float4 s1 = make_float4(x*y, y*z, 3.0f*zz - 1.0f, x*z);
    float4 s2 = make_float4(xx - yy, y*(3.0f*xx - yy), x*y*z, y*(5.0f*zz - 1.0f));
    float4 s3 = make_float4(z*(5.0f*zz - 3.0f), x*(5.0f*zz - 1.0f),
                            z*(xx - yy), x*(xx - 3.0f*yy));
    float4* o = (float4*)(g_sph + t*16);
    o[0] = s0; o[1] = s1; o[2] = s2; o[3] = s3;
}

// ---------------- per-warp (atom, l) work (R7-exact scalar inner loop) ----------------
template<int L, bool HP>
__device__ __forceinline__ void atom_warp(
    const float* sa, const float* sWE, const float2* fe,
    float* sphw,                 // warp-private 512-float slice (sph + scratch)
    float* ge, const float2* tabbase, int i_local, int atom, int lane, int lvl, int s,
    const float* __restrict__ W_agg, const float* __restrict__ W_self,
    const float* __restrict__ W_top, float* anext)
{
    const int M = 2*L + 1;

    float vreg[32];
    #pragma unroll
    for (int d = 0; d < 32; ++d)
        vreg[d] = sa[i_local*CC + d] * sWE[d*CC + lane];

    float accm[M];
    #pragma unroll
    for (int m = 0; m < M; ++m) accm[m] = 0.0f;

    // depth-2 pipeline on table + previous-edge loads
    float2 fe0 = fe[0], fe1 = fe[1];
    float2 tv0 = tabbase[__float_as_int(fe0.y)*512];
    float2 tv1 = tabbase[__float_as_int(fe1.y)*512];
    float gp0 = HP ? ge[lane]      : 0.0f;
    float gp1 = HP ? ge[CC + lane] : 0.0f;

    #pragma unroll 4
    for (int jt = 0; jt < 64; ++jt) {
        float2 fen = make_float2(0.0f, 0.0f);
        float2 tvn = make_float2(0.0f, 0.0f);
        float  gpn = 0.0f;
        if (jt < 62) {
            fen = fe[jt + 2];
            tvn = tabbase[__float_as_int(fen.y)*512];
            if (HP) gpn = ge[(jt+2)*CC + lane];
        }
        const float4* aj4 = (const float4*)(sa + jt*CC);
        float ea0 = gp0, ea1 = 0.f, ea2 = 0.f, ea3 = 0.f;
        #pragma unroll
        for (int q = 0; q < 8; ++q) {
            float4 s4 = aj4[q];
            ea0 = fmaf(s4.x, vreg[4*q+0], ea0);
            ea1 = fmaf(s4.y, vreg[4*q+1], ea1);
            ea2 = fmaf(s4.z, vreg[4*q+2], ea2);
            ea3 = fmaf(s4.w, vreg[4*q+3], ea3);
        }
        float eacc = (ea0 + ea1) + (ea2 + ea3);
        float rad  = fmaf(fe0.x, tv0.y - tv0.x, tv0.x);
        float edge = rad * eacc;
        ge[jt*CC + lane] = edge;

        if (L == 0) {
            accm[0] += edge;
        } else {
            float4 A = *(const float4*)(sphw + jt*8);
            accm[0] = fmaf(edge, A.x, accm[0]);
            if (M > 1) accm[1] = fmaf(edge, A.y, accm[1]);
            if (M > 2) accm[2] = fmaf(edge, A.z, accm[2]);
            if (M > 3) accm[3] = fmaf(edge, A.w, accm[3]);
            if (M > 4) {
                float4 Bq = *(const float4*)(sphw + jt*8 + 4);
                accm[4] = fmaf(edge, Bq.x, accm[4]);
                if (M > 5) accm[5] = fmaf(edge, Bq.y, accm[5]);
                if (M > 6) accm[6] = fmaf(edge, Bq.z, accm[6]);
            }
        }
        fe0 = fe1; fe1 = fen;
        tv0 = tv1; tv1 = tvn;
        gp0 = gp1; gp1 = gpn;
    }

    // ---- per-warp epilogue (reuse warp's sph slice as scratch) ----
    __syncwarp();
    float* wmsg = sphw;
    float* sold = sphw + 256;
    bool has_self = (lvl > 0) || (L == 0);
    #pragma unroll
    for (int m = 0; m < M; ++m) {
        wmsg[m*32 + lane] = accm[m];
        sold[m*32 + lane] = has_self ? g_rep[L][(atom*7 + m)*CC + lane] : 0.0f;
    }
    __syncwarp();

    const float* wa  = W_agg  + s*CC*CC;
    const float* wsf = W_self + s*CC*CC;
    float f, s2 = 0.0f, rep0 = 0.0f;
    #pragma unroll
    for (int m = 0; m < M; ++m) {
        float r = 0.0f, r2 = 0.0f;
        #pragma unroll
        for (int c = 0; c < CC; ++c) {
            r  = fmaf(wmsg[m*32 + c], wa [c*CC + lane], r);
            r2 = fmaf(sold[m*32 + c], wsf[c*CC + lane], r2);
        }
        r += r2;
        g_rep[L][(atom*7 + m)*CC + lane] = r;
        if (m == 0) rep0 = r;
        s2 = fmaf(r, r, s2);
    }
    if (L == 0) {
        anext[atom*CC + lane] = rep0;
        f = rep0;
    } else {
        f = sqrtf(s2 + 1e-12f);
    }
    float part = f * W_top[s*CC + lane];
    #pragma unroll
    for (int off = 16; off; off >>= 1)
        part += __shfl_down_sync(0xffffffffu, part, off);
    if (lane == 0) g_part4[atom*4 + L] += part;
}

// ---------------- one (4-atom group, l) block; warp = one atom ----------------
__global__ void __launch_bounds__(128, 7) k_level(int lvl,
    const float* __restrict__ W_edge, const float* __restrict__ W_agg,
    const float* __restrict__ W_self, const float* __restrict__ W_top)
{
    __shared__ float  sa[NN*CC];        // 8 KB
    __shared__ float  sWE[CC*CC];       // 4 KB
    __shared__ float2 sfe[4*NN];        // 2 KB
    __shared__ float  ssph[4*NN*8];     // 8 KB; warp slices, reused in epilogue

    const float* acur  = g_a[lvl & 1];
    float*       anext = g_a[(lvl + 1) & 1];

    int blk = blockIdx.x;
    int l  = blk & 3;
    int g4 = blk >> 2;
    int b  = g4 >> 4;
    const int M = 2*l + 1;
    int tid = threadIdx.x, w = tid >> 5, lane = tid & 31;
    int atom0 = g4*4;
    int s = lvl*4 + l;

    for (int idx = tid; idx < NN*CC/4; idx += 128)
        ((float4*)sa)[idx] = ((const float4*)(acur + b*NN*CC))[idx];
    {
        const float4* wsrc = (const float4*)(W_edge + s*CC*CC);
        for (int idx = tid; idx < CC*CC/4; idx += 128)
            ((float4*)sWE)[idx] = wsrc[idx];
    }
    for (int t = tid; t < 4*NN; t += 128)
        sfe[t] = g_fe[atom0*NN + t];
    if (l > 0) {
        for (int t = tid; t < 4*NN*8; t += 128) {
            int wi = t >> 9, rem = t & 511, j = rem >> 3, m = rem & 7;
            ssph[t] = (m < M) ? g_sph[((atom0 + wi)*NN + j)*16 + l*l + m] : 0.0f;
        }
    }
    __syncthreads();

    int atom = atom0 + w;
    int i_local = atom & 63;
    float* ge = g_edge[l] + atom*NN*CC;
    const float2* tabbase = g_tab2 + s*32 + lane;
    const float2* fe = sfe + w*NN;
    float* sphw = ssph + w*512;

    if (lvl == 0) {
        switch (l) {
            case 0: atom_warp<0,false>(sa,sWE,fe,sphw,ge,tabbase,i_local,atom,lane,lvl,s,W_agg,W_self,W_top,anext); break;
            case 1: atom_warp<1,false>(sa,sWE,fe,sphw,ge,tabbase,i_local,atom,lane,lvl,s,W_agg,W_self,W_top,anext); break;
            case 2: atom_warp<2,false>(sa,sWE,fe,sphw,ge,tabbase,i_local,atom,lane,lvl,s,W_agg,W_self,W_top,anext); break;
            default:atom_warp<3,false>(sa,sWE,fe,sphw,ge,tabbase,i_local,atom,lane,lvl,s,W_agg,W_self,W_top,anext); break;
        }
    } else {
        switch (l) {
            case 0: atom_warp<0,true >(sa,sWE,fe,sphw,ge,tabbase,i_local,atom,lane,lvl,s,W_agg,W_self,W_top,anext); break;
            case 1: atom_warp<1,true >(sa,sWE,fe,sphw,ge,tabbase,i_local,atom,lane,lvl,s,W_agg,W_self,W_top,anext); break;
            case 2: atom_warp<2,true >(sa,sWE,fe,sphw,ge,tabbase,i_local,atom,lane,lvl,s,W_agg,W_self,W_top,anext); break;
            default:atom_warp<3,true >(sa,sWE,fe,sphw,ge,tabbase,i_local,atom,lane,lvl,s,W_agg,W_self,W_top,anext); break;
        }
    }
}

// ---------------- output ----------------
__global__ void k_out(float* __restrict__ out, const float* __restrict__ b_top) {
    __shared__ float sh[256];
    int b = blockIdx.x, t = threadIdx.x;
    sh[t] = g_part4[b*256 + t];
    __syncthreads();
    #pragma unroll
    for (int off = 128; off; off >>= 1) {
        if (t < off) sh[t] += sh[t + off];
        __syncthreads();
    }
    if (t == 0) out[b] = sh[0] + b_top[0];
}

// ---------------- launch ----------------
extern "C" void kernel_launch(void* const* d_in, const int* in_sizes, int n_in,
                              void* d_out, int out_size) {
    const float* pos     = (const float*)d_in[0];
    const float* oh      = (const float*)d_in[1];
    const int*   charges = (const int*)  d_in[2];
    const float* W_in    = (const float*)d_in[5];
    const float* b_in    = (const float*)d_in[6];
    const float* W_rad   = (const float*)d_in[7];
    const float* W_edge  = (const float*)d_in[8];
    const float* W_agg   = (const float*)d_in[9];
    const float* W_self  = (const float*)d_in[10];
    const float* W_top   = (const float*)d_in[11];
    const float* b_top   = (const float*)d_in[12];

    k_table<<<dim3(33, 16), 256>>>(W_rad);
    k_geom<<<256 + 128, 256>>>(pos, oh, charges, W_in, b_in);
    for (int lvl = 0; lvl < NLVL; ++lvl)
        k_level<<<BB*NN, 128>>>(lvl, W_edge, W_agg, W_self, W_top);
    k_out<<<BB, 256>>>((float*)d_out, b_top);
}

// round 17
// speedup vs baseline: 1.1448x; 1.0388x over previous
#include <cuda_runtime.h>

#define BB 16
#define NN 64
#define CC 32
#define NLVL 4
#define NB 60
#define NE 1024
#define NPAIR (BB*NN*NN)

// ---------------- device scratch (static; no allocs) ----------------
__device__ float g_a[2][BB*NN*CC];
__device__ float g_rep[4][BB*NN*7*CC];
__device__ float g_edge[4][NPAIR*CC];
__device__ float g_sph[NPAIR*16];
__device__ float2 g_fe[NPAIR];            // {frac, bitcast(e0)}
__device__ float g_part4[BB*NN*4];
__device__ float2 g_tab2[(NE+2)*512];     // {val[e], val[e+1]}, row NE+1 = zeros

// ---------------- rad*cut table, basis inline ----------------
__global__ void __launch_bounds__(256) k_table(const float* __restrict__ W_rad) {
    __shared__ float sW[NB*CC];
    __shared__ float sb[64*NB];
    int s   = blockIdx.y;
    int e0b = blockIdx.x * 64;
    int tid = threadIdx.x;
    const float* wr = W_rad + s*NB*CC;
    for (int idx = tid; idx < NB*CC; idx += 256) sW[idx] = wr[idx];
    for (int idx = tid; idx < 64*NB; idx += 256) {
        int row = idx / NB, k = idx - row*NB;
        float r = (float)(e0b + row) * (5.0f/NE);
        float d = r - (float)k * (5.0f/59.0f);
        sb[idx] = expf(-36.0f * d * d);
    }
    __syncthreads();
    int c = tid & 31, eg = tid >> 5;
    float acc[8];
    #pragma unroll
    for (int t = 0; t < 8; ++t) acc[t] = 0.0f;
    for (int k = 0; k < NB; ++k) {
        float wv = sW[k*CC + c];
        #pragma unroll
        for (int t = 0; t < 8; ++t)
            acc[t] = fmaf(sb[(eg*8 + t)*NB + k], wv, acc[t]);
    }
    #pragma unroll
    for (int t = 0; t < 8; ++t) {
        int e = e0b + eg*8 + t;
        if (e <= NE+1) {
            float r = (float)e * (5.0f/NE);
            float cut = 1.0f / (1.0f + __expf((r - 3.0f) * 2.0f));
            float v = (e <= NE) ? acc[t] * cut : 0.0f;   // row NE+1 = hard zero
            g_tab2[e*512 + s*32 + c].x = v;
            if (e > 0) g_tab2[(e-1)*512 + s*32 + c].y = v;
        }
    }
}

// ---------------- geometry + fused input featurization ----------------
__global__ void k_geom(const float* __restrict__ pos,
                       const float* __restrict__ oh, const int* __restrict__ charges,
                       const float* __restrict__ W_in, const float* __restrict__ b_in) {
    if (blockIdx.x >= 256) {   // fused a0 (BB*NN*CC = 32768 threads) + zero g_part4
        int t = (blockIdx.x - 256)*256 + threadIdx.x;   // 0..32767
        int c = t & 31, n = t >> 5;
        float ch = (float)charges[n] * (1.0f/9.0f);
        float p1 = ch, p2 = ch*ch;
        float acc = b_in[c];
        #pragma unroll
        for (int s = 0; s < 5; ++s) {
            float o = oh[n*5 + s];
            acc += o * (W_in[(s*3+0)*CC + c] + p1*W_in[(s*3+1)*CC + c] + p2*W_in[(s*3+2)*CC + c]);
        }
        g_a[0][t] = acc;
        g_rep[0][(n*7 + 0)*CC + c] = acc;
        if (t < BB*NN*4) g_part4[t] = 0.0f;
        return;
    }
    int t = blockIdx.x*256 + threadIdx.x;
    int b = t >> 12, i = (t >> 6) & 63, j = t & 63;
    const float* pi = pos + (b*NN+i)*3;
    const float* pj = pos + (b*NN+j)*3;
    float dx = pi[0]-pj[0], dy = pi[1]-pj[1], dz = pi[2]-pj[2];
    float r = sqrtf(dx*dx + dy*dy + dz*dz + 1e-12f);
    float inv = 1.0f / r;
    float x = dx*inv, y = dy*inv, z = dz*inv;

    bool masked = (i == j) || (r <= 1e-4f) || (r >= 5.0f);
    float fidx = r * ((float)NE / 5.0f);
    int e0 = (int)fidx;
    if (e0 > NE-1) e0 = NE-1;
    float fr = fidx - (float)e0;
    if (fr > 1.0f) fr = 1.0f;
    if (masked) { e0 = NE+1; fr = 0.0f; }
    g_fe[t] = make_float2(fr, __int_as_float(e0));

    float xx = x*x, yy = y*y, zz = z*z;
    float4 s0 = make_float4(1.0f, x, y, z);
    float4 s1 = make_float4(x*y, y*z, 3.0f*zz - 1.0f, x*z);
    float4 s2 = make_float4(xx - yy, y*(3.0f*xx - yy), x*y*z, y*(5.0f*zz - 1.0f));
    float4 s3 = make_float4(z*(5.0f*zz - 3.0f), x*(5.0f*zz - 1.0f),
                            z*(xx - yy), x*(xx - 3.0f*yy));
    float4* o = (float4*)(g_sph + t*16);
    o[0] = s0; o[1] = s1; o[2] = s2; o[3] = s3;
}

// ---------------- per-warp (atom, l) work (R7-exact scalar inner loop) ----------------
template<int L, bool HP, bool ST>
__device__ __forceinline__ void atom_warp(
    const float* sa, const float* sWE, const float2* fe,
    float* sphw,                 // warp-private 512-float slice (sph + scratch)
    float* ge, const float2* tabbase, int i_local, int atom, int lane, int lvl, int s,
    const float* __restrict__ W_agg, const float* __restrict__ W_self,
    const float* __restrict__ W_top, float* anext)
{
    const int M = 2*L + 1;

    float vreg[32];
    #pragma unroll
    for (int d = 0; d < 32; ++d)
        vreg[d] = sa[i_local*CC + d] * sWE[d*CC + lane];

    float accm[M];
    #pragma unroll
    for (int m = 0; m < M; ++m) accm[m] = 0.0f;

    // depth-2 pipeline on table + previous-edge loads
    float2 fe0 = fe[0], fe1 = fe[1];
    float2 tv0 = tabbase[__float_as_int(fe0.y)*512];
    float2 tv1 = tabbase[__float_as_int(fe1.y)*512];
    float gp0 = HP ? ge[lane]      : 0.0f;
    float gp1 = HP ? ge[CC + lane] : 0.0f;

    #pragma unroll 4
    for (int jt = 0; jt < 64; ++jt) {
        float2 fen = make_float2(0.0f, 0.0f);
        float2 tvn = make_float2(0.0f, 0.0f);
        float  gpn = 0.0f;
        if (jt < 62) {
            fen = fe[jt + 2];
            tvn = tabbase[__float_as_int(fen.y)*512];
            if (HP) gpn = ge[(jt+2)*CC + lane];
        }
        const float4* aj4 = (const float4*)(sa + jt*CC);
        float ea0 = gp0, ea1 = 0.f, ea2 = 0.f, ea3 = 0.f;
        #pragma unroll
        for (int q = 0; q < 8; ++q) {
            float4 s4 = aj4[q];
            ea0 = fmaf(s4.x, vreg[4*q+0], ea0);
            ea1 = fmaf(s4.y, vreg[4*q+1], ea1);
            ea2 = fmaf(s4.z, vreg[4*q+2], ea2);
            ea3 = fmaf(s4.w, vreg[4*q+3], ea3);
        }
        float eacc = (ea0 + ea1) + (ea2 + ea3);
        float rad  = fmaf(fe0.x, tv0.y - tv0.x, tv0.x);
        float edge = rad * eacc;
        if (ST) ge[jt*CC + lane] = edge;

        if (L == 0) {
            accm[0] += edge;
        } else {
            float4 A = *(const float4*)(sphw + jt*8);
            accm[0] = fmaf(edge, A.x, accm[0]);
            if (M > 1) accm[1] = fmaf(edge, A.y, accm[1]);
            if (M > 2) accm[2] = fmaf(edge, A.z, accm[2]);
            if (M > 3) accm[3] = fmaf(edge, A.w, accm[3]);
            if (M > 4) {
                float4 Bq = *(const float4*)(sphw + jt*8 + 4);
                accm[4] = fmaf(edge, Bq.x, accm[4]);
                if (M > 5) accm[5] = fmaf(edge, Bq.y, accm[5]);
                if (M > 6) accm[6] = fmaf(edge, Bq.z, accm[6]);
            }
        }
        fe0 = fe1; fe1 = fen;
        tv0 = tv1; tv1 = tvn;
        gp0 = gp1; gp1 = gpn;
    }

    // ---- per-warp epilogue (reuse warp's sph slice as scratch) ----
    __syncwarp();
    float* wmsg = sphw;
    float* sold = sphw + 256;
    bool has_self = (lvl > 0) || (L == 0);
    #pragma unroll
    for (int m = 0; m < M; ++m) {
        wmsg[m*32 + lane] = accm[m];
        sold[m*32 + lane] = has_self ? g_rep[L][(atom*7 + m)*CC + lane] : 0.0f;
    }
    __syncwarp();

    const float* wa  = W_agg  + s*CC*CC;
    const float* wsf = W_self + s*CC*CC;
    float f, s2 = 0.0f, rep0 = 0.0f;
    #pragma unroll
    for (int m = 0; m < M; ++m) {
        float r = 0.0f, r2 = 0.0f;
        #pragma unroll
        for (int c = 0; c < CC; ++c) {
            r  = fmaf(wmsg[m*32 + c], wa [c*CC + lane], r);
            r2 = fmaf(sold[m*32 + c], wsf[c*CC + lane], r2);
        }
        r += r2;
        g_rep[L][(atom*7 + m)*CC + lane] = r;
        if (m == 0) rep0 = r;
        s2 = fmaf(r, r, s2);
    }
    if (L == 0) {
        anext[atom*CC + lane] = rep0;
        f = rep0;
    } else {
        f = sqrtf(s2 + 1e-12f);
    }
    float part = f * W_top[s*CC + lane];
    #pragma unroll
    for (int off = 16; off; off >>= 1)
        part += __shfl_down_sync(0xffffffffu, part, off);
    if (lane == 0) g_part4[atom*4 + L] += part;
}

// ---------------- one (4-atom group, l) block; warp = one atom ----------------
__global__ void __launch_bounds__(128, 7) k_level(int lvl,
    const float* __restrict__ W_edge, const float* __restrict__ W_agg,
    const float* __restrict__ W_self, const float* __restrict__ W_top)
{
    __shared__ float  sa[NN*CC];        // 8 KB
    __shared__ float  sWE[CC*CC];       // 4 KB
    __shared__ float2 sfe[4*NN];        // 2 KB
    __shared__ float  ssph[4*NN*8];     // 8 KB; warp slices, reused in epilogue

    const float* acur  = g_a[lvl & 1];
    float*       anext = g_a[(lvl + 1) & 1];

    int blk = blockIdx.x;
    int l  = blk & 3;
    int g4 = blk >> 2;
    int b  = g4 >> 4;
    const int M = 2*l + 1;
    int tid = threadIdx.x, w = tid >> 5, lane = tid & 31;
    int atom0 = g4*4;
    int s = lvl*4 + l;

    for (int idx = tid; idx < NN*CC/4; idx += 128)
        ((float4*)sa)[idx] = ((const float4*)(acur + b*NN*CC))[idx];
    {
        const float4* wsrc = (const float4*)(W_edge + s*CC*CC);
        for (int idx = tid; idx < CC*CC/4; idx += 128)
            ((float4*)sWE)[idx] = wsrc[idx];
    }
    for (int t = tid; t < 4*NN; t += 128)
        sfe[t] = g_fe[atom0*NN + t];
    if (l > 0) {
        for (int t = tid; t < 4*NN*8; t += 128) {
            int wi = t >> 9, rem = t & 511, j = rem >> 3, m = rem & 7;
            ssph[t] = (m < M) ? g_sph[((atom0 + wi)*NN + j)*16 + l*l + m] : 0.0f;
        }
    }
    __syncthreads();

    int atom = atom0 + w;
    int i_local = atom & 63;
    float* ge = g_edge[l] + atom*NN*CC;
    const float2* tabbase = g_tab2 + s*32 + lane;
    const float2* fe = sfe + w*NN;
    float* sphw = ssph + w*512;

    if (lvl == 0) {
        switch (l) {
            case 0: atom_warp<0,false,true>(sa,sWE,fe,sphw,ge,tabbase,i_local,atom,lane,lvl,s,W_agg,W_self,W_top,anext); break;
            case 1: atom_warp<1,false,true>(sa,sWE,fe,sphw,ge,tabbase,i_local,atom,lane,lvl,s,W_agg,W_self,W_top,anext); break;
            case 2: atom_warp<2,false,true>(sa,sWE,fe,sphw,ge,tabbase,i_local,atom,lane,lvl,s,W_agg,W_self,W_top,anext); break;
            default:atom_warp<3,false,true>(sa,sWE,fe,sphw,ge,tabbase,i_local,atom,lane,lvl,s,W_agg,W_self,W_top,anext); break;
        }
    } else if (lvl < 3) {
        switch (l) {
            case 0: atom_warp<0,true,true >(sa,sWE,fe,sphw,ge,tabbase,i_local,atom,lane,lvl,s,W_agg,W_self,W_top,anext); break;
            case 1: atom_warp<1,true,true >(sa,sWE,fe,sphw,ge,tabbase,i_local,atom,lane,lvl,s,W_agg,W_self,W_top,anext); break;
            case 2: atom_warp<2,true,true >(sa,sWE,fe,sphw,ge,tabbase,i_local,atom,lane,lvl,s,W_agg,W_self,W_top,anext); break;
            default:atom_warp<3,true,true >(sa,sWE,fe,sphw,ge,tabbase,i_local,atom,lane,lvl,s,W_agg,W_self,W_top,anext); break;
        }
    } else {   // last level: edges never read again -> skip the store
        switch (l) {
            case 0: atom_warp<0,true,false>(sa,sWE,fe,sphw,ge,tabbase,i_local,atom,lane,lvl,s,W_agg,W_self,W_top,anext); break;
            case 1: atom_warp<1,true,false>(sa,sWE,fe,sphw,ge,tabbase,i_local,atom,lane,lvl,s,W_agg,W_self,W_top,anext); break;
            case 2: atom_warp<2,true,false>(sa,sWE,fe,sphw,ge,tabbase,i_local,atom,lane,lvl,s,W_agg,W_self,W_top,anext); break;
            default:atom_warp<3,true,false>(sa,sWE,fe,sphw,ge,tabbase,i_local,atom,lane,lvl,s,W_agg,W_self,W_top,anext); break;
        }
    }
}

// ---------------- output ----------------
__global__ void k_out(float* __restrict__ out, const float* __restrict__ b_top) {
    __shared__ float sh[256];
    int b = blockIdx.x, t = threadIdx.x;
    sh[t] = g_part4[b*256 + t];
    __syncthreads();
    #pragma unroll
    for (int off = 128; off; off >>= 1) {
        if (t < off) sh[t] += sh[t + off];
        __syncthreads();
    }
    if (t == 0) out[b] = sh[0] + b_top[0];
}

// ---------------- launch ----------------
extern "C" void kernel_launch(void* const* d_in, const int* in_sizes, int n_in,
                              void* d_out, int out_size) {
    const float* pos     = (const float*)d_in[0];
    const float* oh      = (const float*)d_in[1];
    const int*   charges = (const int*)  d_in[2];
    const float* W_in    = (const float*)d_in[5];
    const float* b_in    = (const float*)d_in[6];
    const float* W_rad   = (const float*)d_in[7];
    const float* W_edge  = (const float*)d_in[8];
    const float* W_agg   = (const float*)d_in[9];
    const float* W_self  = (const float*)d_in[10];
    const float* W_top   = (const float*)d_in[11];
    const float* b_top   = (const float*)d_in[12];

    k_table<<<dim3(NE/64 + 1, 16), 256>>>(W_rad);
    k_geom<<<256 + 128, 256>>>(pos, oh, charges, W_in, b_in);
    for (int lvl = 0; lvl < NLVL; ++lvl)
        k_level<<<BB*NN, 128>>>(lvl, W_edge, W_agg, W_self, W_top);
    k_out<<<BB, 256>>>((float*)d_out, b_top);
}